// round 4
// baseline (speedup 1.0000x reference)
#include <cuda_runtime.h>
#include <math.h>

// Problem constants
#define Hd 1024
#define Vd 4096
#define Bd 64
#define Td 512
#define BT (Bd*Td)       // 32768
#define NBLK 128         // persistent CTAs (one per SM, <=148)
#define JPB 8            // output columns per CTA (128*8 = 1024)

// Scratch (device globals; no runtime allocation)
__device__ float g_abase[(size_t)BT*Hd];   // (t,b,h) pre-activation x_emb + b
__device__ float g_hs[(size_t)BT*Hd];      // (t,b,h) hidden states
__device__ unsigned g_bar_count;           // grid barrier state (self-resetting)
__device__ unsigned g_bar_gen;             // monotonic generation

// ---------------------------------------------------------------------------
// K1: embedding gather + bias  a_base[(t*B+b), :] = wxh[X[b,t], :] + bvec
// ---------------------------------------------------------------------------
__global__ void embed_kernel(const int* __restrict__ X,
                             const float* __restrict__ wxh,
                             const float* __restrict__ bvec) {
    int r = blockIdx.x;            // r = t*B + b
    int t = r >> 6;
    int b = r & 63;
    int row = X[b * Td + t];
    const float4* src = (const float4*)(wxh + (size_t)row * Hd);
    const float4* bb  = (const float4*)bvec;
    float4* dst = (float4*)(g_abase + (size_t)r * Hd);
    int i = threadIdx.x;           // 256 = H/4
    float4 v = src[i];
    float4 w = bb[i];
    v.x += w.x; v.y += w.y; v.z += w.z; v.w += w.w;
    dst[i] = v;
}

// ---------------------------------------------------------------------------
// Grid barrier: sense-reversing via (count, gen). All NBLK CTAs must be
// co-resident (they are: 128 CTAs, one per SM). Deterministic.
// ---------------------------------------------------------------------------
__device__ __forceinline__ void grid_barrier(int tid) {
    __syncthreads();
    if (tid == 0) {
        unsigned gen = *(volatile unsigned*)&g_bar_gen;  // read BEFORE arrive
        __threadfence();                                 // publish my writes
        unsigned prev = atomicAdd(&g_bar_count, 1u);
        if (prev == NBLK - 1u) {
            atomicExch(&g_bar_count, 0u);                // reset for next use
            __threadfence();
            atomicExch(&g_bar_gen, gen + 1u);            // release
        } else {
            while (*(volatile unsigned*)&g_bar_gen == gen) __nanosleep(32);
        }
        __threadfence();                                 // acquire
    }
    __syncthreads();
}

// ---------------------------------------------------------------------------
// K2: persistent recurrence. CTA bid owns output columns j0 = bid*8 .. +8.
// W_hh slice (8 x 1024) lives in smem for all 512 steps.
// Per step: 8 warps split K (128 each); thread computes 4b x 4j register
// tile; cross-warp reduce via smem; tanh fused; grid barrier between steps.
// ---------------------------------------------------------------------------
__global__ void __launch_bounds__(256, 1)
rnn_persistent(const float* __restrict__ whh) {
    __shared__ float Wsl[JPB * Hd];     // 32 KB: Wsl[m*1024 + k] = whh[(j0+m)*1024 + k]
    __shared__ float red[8 * 512];      // 16 KB: red[w*512 + ln*16 + idx]

    const int bid = blockIdx.x;         // 0..127
    const int j0  = bid * JPB;
    const int tid = threadIdx.x;
    const int w   = tid >> 5;           // warp 0..7
    const int ln  = tid & 31;

    // Load W_hh slice (rows j0..j0+7 are contiguous in gmem): 8192 floats
    {
        const float4* src = (const float4*)(whh + (size_t)j0 * Hd);
        float4* dst = (float4*)Wsl;
        #pragma unroll
        for (int i = 0; i < 8; i++) dst[tid + i * 256] = src[tid + i * 256];
    }

    // h_0 = tanh(a_base[0]) for this CTA's columns (2 elems/thread)
    #pragma unroll
    for (int e = 0; e < 2; e++) {
        int o = tid * 2 + e;
        int b = o >> 3, j = o & 7;
        g_hs[(size_t)b * Hd + j0 + j] = tanhf(g_abase[(size_t)b * Hd + j0 + j]);
    }

    // per-warp geometry
    const int kb   = w * 128;           // this warp's K chunk
    const int bgrp = ln >> 1;           // 0..15
    const int brow = bgrp * 4;          // 4 consecutive batch rows
    const int jcol = (ln & 1) * 4;      // 0 or 4

    for (int t = 1; t < Td; t++) {
        grid_barrier(tid);   // h_{t-1} visible everywhere; also guards red reuse

        const float* hp = g_hs + (size_t)(t - 1) * (Bd * Hd);
        const float* hbase = hp + (size_t)brow * Hd + kb;

        float acc[4][4];
        #pragma unroll
        for (int i = 0; i < 4; i++)
            #pragma unroll
            for (int m = 0; m < 4; m++) acc[i][m] = 0.0f;

        // double-buffered h prefetch over 32 groups of 4 k
        float4 h4[2][4];
        #pragma unroll
        for (int i = 0; i < 4; i++)
            h4[0][i] = *(const float4*)(hbase + (size_t)i * Hd);

        for (int kc = 0; kc < 32; kc++) {
            int cur = kc & 1, nxt = cur ^ 1;
            if (kc < 31) {
                #pragma unroll
                for (int i = 0; i < 4; i++)
                    h4[nxt][i] = *(const float4*)(hbase + (size_t)i * Hd + (kc + 1) * 4);
            }
            float4 w4[4];
            #pragma unroll
            for (int m = 0; m < 4; m++)
                w4[m] = *(const float4*)&Wsl[(jcol + m) * Hd + kb + kc * 4];
            #pragma unroll
            for (int i = 0; i < 4; i++) {
                float4 hv = h4[cur][i];
                #pragma unroll
                for (int m = 0; m < 4; m++) {
                    acc[i][m] = fmaf(hv.x, w4[m].x, acc[i][m]);
                    acc[i][m] = fmaf(hv.y, w4[m].y, acc[i][m]);
                    acc[i][m] = fmaf(hv.z, w4[m].z, acc[i][m]);
                    acc[i][m] = fmaf(hv.w, w4[m].w, acc[i][m]);
                }
            }
        }

        // store partials thread-contiguous (conflict-free STS.128)
        float* myred = &red[w * 512 + ln * 16];
        #pragma unroll
        for (int i = 0; i < 4; i++)
            *(float4*)&myred[i * 4] =
                make_float4(acc[i][0], acc[i][1], acc[i][2], acc[i][3]);
        __syncthreads();

        // reduce 8 warps, add a_base, tanh, write h_t (2 outputs/thread)
        const float* ab = g_abase + (size_t)t * (Bd * Hd);
        float* hout = g_hs + (size_t)t * (Bd * Hd);
        #pragma unroll
        for (int e = 0; e < 2; e++) {
            int o = tid * 2 + e;
            int b = o >> 3, j = o & 7;
            int lane2 = (b >> 2) * 2 + (j >> 2);
            int idx   = (b & 3) * 4 + (j & 3);
            float s = ab[(size_t)b * Hd + j0 + j];
            #pragma unroll
            for (int ww = 0; ww < 8; ww++)
                s += red[ww * 512 + lane2 * 16 + idx];
            hout[(size_t)b * Hd + j0 + j] = tanhf(s);
        }
        // next grid_barrier's __syncthreads guards red before overwrite
    }
}

// ---------------------------------------------------------------------------
// K4: big output GEMM  z[r, v] = sum_k Hs[r, k] * Wvh[v, k] + c[v]
// written directly into outs region with row remap r=(t*B+b) -> (b*T+t)
// BM=128, BN=128, TK=16, 256 threads, 8x8 microtile.
// ---------------------------------------------------------------------------
__global__ void vh_gemm_kernel(const float* __restrict__ wvh,
                               const float* __restrict__ cvec,
                               float* __restrict__ outp) {
    __shared__ float A_s[16][132];
    __shared__ float B_s[16][132];
    const int v0 = blockIdx.x * 128;
    const int r0 = blockIdx.y * 128;
    const int tid = threadIdx.x;
    const int tx = tid & 15;
    const int ty = tid >> 4;

    float acc[8][8];
    #pragma unroll
    for (int i = 0; i < 8; i++)
        #pragma unroll
        for (int j = 0; j < 8; j++) acc[i][j] = 0.0f;

    const int lrow = tid >> 2;        // 0..63
    const int lk4  = (tid & 3) * 4;

    for (int kc = 0; kc < 64; ++kc) {
        int k0 = kc * 16;
        float4 a0 = *(const float4*)(g_hs + (size_t)(r0 + lrow) * Hd + k0 + lk4);
        float4 a1 = *(const float4*)(g_hs + (size_t)(r0 + lrow + 64) * Hd + k0 + lk4);
        float4 b0 = *(const float4*)(wvh + (size_t)(v0 + lrow) * Hd + k0 + lk4);
        float4 b1 = *(const float4*)(wvh + (size_t)(v0 + lrow + 64) * Hd + k0 + lk4);
        __syncthreads();
        A_s[lk4 + 0][lrow] = a0.x; A_s[lk4 + 1][lrow] = a0.y;
        A_s[lk4 + 2][lrow] = a0.z; A_s[lk4 + 3][lrow] = a0.w;
        A_s[lk4 + 0][lrow + 64] = a1.x; A_s[lk4 + 1][lrow + 64] = a1.y;
        A_s[lk4 + 2][lrow + 64] = a1.z; A_s[lk4 + 3][lrow + 64] = a1.w;
        B_s[lk4 + 0][lrow] = b0.x; B_s[lk4 + 1][lrow] = b0.y;
        B_s[lk4 + 2][lrow] = b0.z; B_s[lk4 + 3][lrow] = b0.w;
        B_s[lk4 + 0][lrow + 64] = b1.x; B_s[lk4 + 1][lrow + 64] = b1.y;
        B_s[lk4 + 2][lrow + 64] = b1.z; B_s[lk4 + 3][lrow + 64] = b1.w;
        __syncthreads();
        #pragma unroll
        for (int kk = 0; kk < 16; ++kk) {
            float4 af0 = *(const float4*)&A_s[kk][ty * 8];
            float4 af1 = *(const float4*)&A_s[kk][ty * 8 + 4];
            float4 wf0 = *(const float4*)&B_s[kk][tx * 8];
            float4 wf1 = *(const float4*)&B_s[kk][tx * 8 + 4];
            float a[8] = {af0.x, af0.y, af0.z, af0.w, af1.x, af1.y, af1.z, af1.w};
            float w[8] = {wf0.x, wf0.y, wf0.z, wf0.w, wf1.x, wf1.y, wf1.z, wf1.w};
            #pragma unroll
            for (int i = 0; i < 8; i++)
                #pragma unroll
                for (int j = 0; j < 8; j++)
                    acc[i][j] = fmaf(a[i], w[j], acc[i][j]);
        }
    }

    float cl[8];
    #pragma unroll
    for (int j = 0; j < 8; j++) cl[j] = cvec[v0 + tx * 8 + j];

    #pragma unroll
    for (int i = 0; i < 8; i++) {
        int r = r0 + ty * 8 + i;
        int orow = (r & 63) * Td + (r >> 6);   // b*T + t
        float* op = outp + (size_t)orow * Vd + v0 + tx * 8;
        float4 o0 = make_float4(acc[i][0] + cl[0], acc[i][1] + cl[1],
                                acc[i][2] + cl[2], acc[i][3] + cl[3]);
        float4 o1 = make_float4(acc[i][4] + cl[4], acc[i][5] + cl[5],
                                acc[i][6] + cl[6], acc[i][7] + cl[7]);
        *(float4*)op = o0;
        *(float4*)(op + 4) = o1;
    }
}

// ---------------------------------------------------------------------------
// K5: in-place log_softmax over rows of 4096. One block (256 thr) per row.
// ---------------------------------------------------------------------------
__global__ void logsoftmax_kernel(float* __restrict__ outp) {
    float* row = outp + (size_t)blockIdx.x * Vd;
    const int tid = threadIdx.x;
    const int lane = tid & 31;
    const int wid = tid >> 5;
    __shared__ float sred[8];

    float4 v[4];
    float mx = -1e30f;
    #pragma unroll
    for (int i = 0; i < 4; i++) {
        v[i] = *(const float4*)(row + (i * 256 + tid) * 4);
        mx = fmaxf(mx, fmaxf(fmaxf(v[i].x, v[i].y), fmaxf(v[i].z, v[i].w)));
    }
    #pragma unroll
    for (int o = 16; o; o >>= 1) mx = fmaxf(mx, __shfl_xor_sync(0xffffffffu, mx, o));
    if (lane == 0) sred[wid] = mx;
    __syncthreads();
    float m2 = sred[lane & 7];
    #pragma unroll
    for (int o = 4; o; o >>= 1) m2 = fmaxf(m2, __shfl_xor_sync(0xffffffffu, m2, o));
    mx = m2;
    __syncthreads();

    float sum = 0.0f;
    #pragma unroll
    for (int i = 0; i < 4; i++) {
        sum += expf(v[i].x - mx) + expf(v[i].y - mx)
             + expf(v[i].z - mx) + expf(v[i].w - mx);
    }
    #pragma unroll
    for (int o = 16; o; o >>= 1) sum += __shfl_xor_sync(0xffffffffu, sum, o);
    if (lane == 0) sred[wid] = sum;
    __syncthreads();
    float s2 = sred[lane & 7];
    #pragma unroll
    for (int o = 4; o; o >>= 1) s2 += __shfl_xor_sync(0xffffffffu, s2, o);

    float lse = mx + logf(s2);
    #pragma unroll
    for (int i = 0; i < 4; i++) {
        v[i].x -= lse; v[i].y -= lse; v[i].z -= lse; v[i].w -= lse;
        *(float4*)(row + (i * 256 + tid) * 4) = v[i];
    }
}

// ---------------------------------------------------------------------------
// K6: hiddens transpose  outh[h, r] = g_hs[r, h]   (r = t*B+b)
// ---------------------------------------------------------------------------
__global__ void transpose_kernel(float* __restrict__ outh) {
    __shared__ float tile[32][33];
    const int h0 = blockIdx.x * 32;
    const int r0 = blockIdx.y * 32;
    const int tx = threadIdx.x;
    const int ty = threadIdx.y;
    #pragma unroll
    for (int i = 0; i < 32; i += 8)
        tile[ty + i][tx] = g_hs[(size_t)(r0 + ty + i) * Hd + h0 + tx];
    __syncthreads();
    #pragma unroll
    for (int i = 0; i < 32; i += 8)
        outh[(size_t)(h0 + ty + i) * BT + r0 + tx] = tile[tx][ty + i];
}

// ---------------------------------------------------------------------------
extern "C" void kernel_launch(void* const* d_in, const int* in_sizes, int n_in,
                              void* d_out, int out_size) {
    const int*   X   = nullptr;
    const float* wxh = nullptr;
    const float* whh = nullptr;
    const float* wvh = nullptr;
    const float* bv  = nullptr;
    const float* cv  = nullptr;

    for (int i = 0; i < n_in; i++) {
        int s = in_sizes[i];
        if (s == BT && !X)            X   = (const int*)d_in[i];
        else if (s == Hd * Hd)        whh = (const float*)d_in[i];
        else if (s == Hd)             bv  = (const float*)d_in[i];
        else if (s == Vd)             cv  = (const float*)d_in[i];
        else if (s == Vd * Hd) {
            if (!wxh) wxh = (const float*)d_in[i];
            else      wvh = (const float*)d_in[i];
        }
    }

    float* outp = (float*)d_out;
    float* outs = outp;                       // (B, T, V) log-probs
    float* outh = outp + (size_t)BT * Vd;     // (H, T, B) hiddens

    // 1) embedding gather + bias
    embed_kernel<<<BT, 256>>>(X, wxh, bv);
    // 2) full recurrence in ONE persistent kernel (grid barrier between steps)
    rnn_persistent<<<NBLK, 256>>>(whh);
    // 3) output projection (writes z into outs with row remap)
    vh_gemm_kernel<<<dim3(Vd / 128, BT / 128), 256>>>(wvh, cv, outs);
    // 4) log_softmax in place
    logsoftmax_kernel<<<BT, 256>>>(outs);
    // 5) hiddens transpose
    transpose_kernel<<<dim3(Hd / 32, BT / 32), dim3(32, 8)>>>(outh);
}

// round 5
// speedup vs baseline: 1.1595x; 1.1595x over previous
#include <cuda_runtime.h>
#include <math.h>
#include <stdint.h>

// Problem constants
#define Hd 1024
#define Vd 4096
#define Bd 64
#define Td 512
#define BT (Bd*Td)       // 32768
#define NBLK 128         // persistent CTAs (one per SM, <=148 => all co-resident)
#define JPB 8            // output columns per CTA (128*8 = 1024)
#define NW 16            // warps per CTA in persistent kernel

// Scratch (device globals; no runtime allocation)
__device__ float g_abase[(size_t)BT*Hd];   // (t,b,h) pre-activation x_emb + b
__device__ float g_hs[(size_t)BT*Hd];      // (t,b,h) hidden states
__device__ unsigned g_bar_count;           // grid barrier state (self-resetting)
__device__ unsigned g_bar_gen;             // monotonic generation

// ---------------------------------------------------------------------------
// K1: embedding gather + bias  a_base[(t*B+b), :] = wxh[X[b,t], :] + bvec
// ---------------------------------------------------------------------------
__global__ void embed_kernel(const int* __restrict__ X,
                             const float* __restrict__ wxh,
                             const float* __restrict__ bvec) {
    int r = blockIdx.x;            // r = t*B + b
    int t = r >> 6;
    int b = r & 63;
    int row = X[b * Td + t];
    const float4* src = (const float4*)(wxh + (size_t)row * Hd);
    const float4* bb  = (const float4*)bvec;
    float4* dst = (float4*)(g_abase + (size_t)r * Hd);
    int i = threadIdx.x;           // 256 = H/4
    float4 v = src[i];
    float4 w = bb[i];
    v.x += w.x; v.y += w.y; v.z += w.z; v.w += w.w;
    dst[i] = v;
}

// ---------------------------------------------------------------------------
// Grid barrier: sense-reversing (count, gen). All NBLK CTAs co-resident.
// NO nanosleep — plain L2 poll (detection latency ~300 cyc).
// ---------------------------------------------------------------------------
__device__ __forceinline__ void grid_barrier(int tid) {
    __syncthreads();
    if (tid == 0) {
        unsigned gen = *(volatile unsigned*)&g_bar_gen;  // read BEFORE arrive
        __threadfence();                                 // publish my writes
        unsigned prev = atomicAdd(&g_bar_count, 1u);
        if (prev == NBLK - 1u) {
            atomicExch(&g_bar_count, 0u);                // reset for next use
            __threadfence();
            atomicExch(&g_bar_gen, gen + 1u);            // release
        } else {
            while (*(volatile unsigned*)&g_bar_gen == gen) { }
        }
        __threadfence();                                 // acquire
    }
    __syncthreads();
}

// ---------------------------------------------------------------------------
// K2: persistent recurrence. CTA owns 8 output columns; W_hh slice (8x1024,
// 32KB) resident in smem for all 512 steps. 16 warps, each K-chunk of 64.
// Thread tile 4(batch) x 4(col). Cross-warp reduce via smem (conflict-free),
// tanh fused, grid barrier between steps. Dynamic smem = 64KB.
// ---------------------------------------------------------------------------
__global__ void __launch_bounds__(512, 1)
rnn_persistent(const float* __restrict__ whh) {
    extern __shared__ float dsm[];
    float* Wsl = dsm;               // [8*1024]  Wsl[m*1024+k] = whh[(j0+m)*1024+k]
    float* red = dsm + JPB * Hd;    // [16*512]  red[w*512 + i*128 + ln*4 + m]

    const int bid = blockIdx.x;     // 0..127
    const int j0  = bid * JPB;
    const int tid = threadIdx.x;
    const int w   = tid >> 5;       // warp 0..15
    const int ln  = tid & 31;

    // Load W_hh slice (rows j0..j0+7 contiguous): 8192 floats = 2048 float4
    {
        const float4* src = (const float4*)(whh + (size_t)j0 * Hd);
        float4* dst = (float4*)Wsl;
        #pragma unroll
        for (int i = 0; i < 4; i++) dst[tid + i * 512] = src[tid + i * 512];
    }

    // h_0 = tanh(a_base[0]) for this CTA's columns (1 elem/thread)
    {
        int b = tid >> 3, j = tid & 7;
        g_hs[(size_t)b * Hd + j0 + j] = tanhf(g_abase[(size_t)b * Hd + j0 + j]);
    }

    // per-warp geometry: warp w covers K chunk [w*64, w*64+64)
    const int kb   = w * 64;
    const int brow = (ln >> 1) * 4;     // 4 consecutive batch rows
    const int jcol = (ln & 1) * 4;      // 0 or 4

    for (int t = 1; t < Td; t++) {
        grid_barrier(tid);   // h_{t-1} visible everywhere; also guards red reuse

        const float* hbase = g_hs + (size_t)(t - 1) * (Bd * Hd)
                                  + (size_t)brow * Hd + kb;

        float acc[4][4];
        #pragma unroll
        for (int i = 0; i < 4; i++)
            #pragma unroll
            for (int m = 0; m < 4; m++) acc[i][m] = 0.0f;

        // double-buffered h prefetch over 16 groups of 4 k (L2-only loads)
        float4 h4[2][4];
        #pragma unroll
        for (int i = 0; i < 4; i++)
            h4[0][i] = __ldcg((const float4*)(hbase + (size_t)i * Hd));

        for (int kc = 0; kc < 16; kc++) {
            int cur = kc & 1, nxt = cur ^ 1;
            if (kc < 15) {
                #pragma unroll
                for (int i = 0; i < 4; i++)
                    h4[nxt][i] = __ldcg((const float4*)(hbase + (size_t)i * Hd + (kc + 1) * 4));
            }
            float4 w4[4];
            #pragma unroll
            for (int m = 0; m < 4; m++)
                w4[m] = *(const float4*)&Wsl[(jcol + m) * Hd + kb + kc * 4];
            #pragma unroll
            for (int i = 0; i < 4; i++) {
                float4 hv = h4[cur][i];
                #pragma unroll
                for (int m = 0; m < 4; m++) {
                    acc[i][m] = fmaf(hv.x, w4[m].x, acc[i][m]);
                    acc[i][m] = fmaf(hv.y, w4[m].y, acc[i][m]);
                    acc[i][m] = fmaf(hv.z, w4[m].z, acc[i][m]);
                    acc[i][m] = fmaf(hv.w, w4[m].w, acc[i][m]);
                }
            }
        }

        // store partials: red[w*512 + i*128 + ln*4 + m]  (STS.128 conflict-free)
        {
            float* myred = &red[w * 512 + ln * 4];
            #pragma unroll
            for (int i = 0; i < 4; i++)
                *(float4*)&myred[i * 128] =
                    make_float4(acc[i][0], acc[i][1], acc[i][2], acc[i][3]);
        }
        __syncthreads();

        // reduce 16 warps, add a_base, tanh, write h_t (1 output/thread)
        {
            int b = tid >> 3, j = tid & 7;
            int idx = (b & 3) * 128 + ((b >> 2) * 2 + (j >> 2)) * 4 + (j & 3);
            float s = g_abase[(size_t)t * (Bd * Hd) + (size_t)b * Hd + j0 + j];
            #pragma unroll
            for (int ww = 0; ww < NW; ww++)
                s += red[ww * 512 + idx];
            g_hs[(size_t)t * (Bd * Hd) + (size_t)b * Hd + j0 + j] = tanhf(s);
        }
        // next grid_barrier's __syncthreads guards red before overwrite
    }
}

// ---------------------------------------------------------------------------
// K4: output GEMM on tf32 tensor cores.
// z[r, v] = sum_k Hs[r,k] * Wvh[v,k] + c[v], row remap r=(t*B+b) -> (b*T+t).
// BM=128, BN=128, BK=16. 8 warps as 4(m) x 2(n); warp tile 32x64 =
// 2 x 8 tiles of m16n8k8. A row-major, B col-major (wvh rows ARE B columns).
// ---------------------------------------------------------------------------
__device__ __forceinline__ uint32_t f2tf32(float x) {
    uint32_t r;
    asm("cvt.rna.tf32.f32 %0, %1;" : "=r"(r) : "f"(x));
    return r;
}
__device__ __forceinline__ void mma_tf32(float c[4], uint32_t a0, uint32_t a1,
                                         uint32_t a2, uint32_t a3,
                                         uint32_t b0, uint32_t b1) {
    asm volatile(
        "mma.sync.aligned.m16n8k8.row.col.f32.tf32.tf32.f32 "
        "{%0,%1,%2,%3}, {%4,%5,%6,%7}, {%8,%9}, {%0,%1,%2,%3};"
        : "+f"(c[0]), "+f"(c[1]), "+f"(c[2]), "+f"(c[3])
        : "r"(a0), "r"(a1), "r"(a2), "r"(a3), "r"(b0), "r"(b1));
}

#define LDA 136   // pad: conflict-free fragment loads (136 % 32 == 8)

__global__ void __launch_bounds__(256, 1)
vh_gemm_tf32(const float* __restrict__ wvh,
             const float* __restrict__ cvec,
             float* __restrict__ outp) {
    __shared__ uint32_t A_s[16][LDA];
    __shared__ uint32_t B_s[16][LDA];
    const int v0 = blockIdx.x * 128;
    const int r0 = blockIdx.y * 128;
    const int tid  = threadIdx.x;
    const int warp = tid >> 5;
    const int lane = tid & 31;
    const int warp_m = warp & 3;        // 4 m-warps
    const int warp_n = warp >> 2;       // 2 n-warps
    const int m_base = warp_m * 32;
    const int n_base = warp_n * 64;
    const int lq = lane >> 2;           // 0..7
    const int lr = lane & 3;            // 0..3

    float acc[2][8][4];
    #pragma unroll
    for (int mt = 0; mt < 2; mt++)
        #pragma unroll
        for (int nt = 0; nt < 8; nt++)
            #pragma unroll
            for (int e = 0; e < 4; e++) acc[mt][nt][e] = 0.0f;

    const int lrow = tid >> 2;          // 0..63
    const int lk4  = (tid & 3) * 4;

    for (int kc = 0; kc < 64; ++kc) {
        int k0 = kc * 16;
        float4 a0 = *(const float4*)(g_hs + (size_t)(r0 + lrow) * Hd + k0 + lk4);
        float4 a1 = *(const float4*)(g_hs + (size_t)(r0 + lrow + 64) * Hd + k0 + lk4);
        float4 b0 = *(const float4*)(wvh + (size_t)(v0 + lrow) * Hd + k0 + lk4);
        float4 b1 = *(const float4*)(wvh + (size_t)(v0 + lrow + 64) * Hd + k0 + lk4);
        __syncthreads();
        A_s[lk4 + 0][lrow] = f2tf32(a0.x); A_s[lk4 + 1][lrow] = f2tf32(a0.y);
        A_s[lk4 + 2][lrow] = f2tf32(a0.z); A_s[lk4 + 3][lrow] = f2tf32(a0.w);
        A_s[lk4 + 0][lrow + 64] = f2tf32(a1.x); A_s[lk4 + 1][lrow + 64] = f2tf32(a1.y);
        A_s[lk4 + 2][lrow + 64] = f2tf32(a1.z); A_s[lk4 + 3][lrow + 64] = f2tf32(a1.w);
        B_s[lk4 + 0][lrow] = f2tf32(b0.x); B_s[lk4 + 1][lrow] = f2tf32(b0.y);
        B_s[lk4 + 2][lrow] = f2tf32(b0.z); B_s[lk4 + 3][lrow] = f2tf32(b0.w);
        B_s[lk4 + 0][lrow + 64] = f2tf32(b1.x); B_s[lk4 + 1][lrow + 64] = f2tf32(b1.y);
        B_s[lk4 + 2][lrow + 64] = f2tf32(b1.z); B_s[lk4 + 3][lrow + 64] = f2tf32(b1.w);
        __syncthreads();

        #pragma unroll
        for (int ks = 0; ks < 2; ks++) {
            int kq = ks * 8 + lr;
            uint32_t afr[2][4];
            #pragma unroll
            for (int mt = 0; mt < 2; mt++) {
                int row = m_base + mt * 16 + lq;
                afr[mt][0] = A_s[kq][row];
                afr[mt][1] = A_s[kq][row + 8];
                afr[mt][2] = A_s[kq + 4][row];
                afr[mt][3] = A_s[kq + 4][row + 8];
            }
            uint32_t bfr[8][2];
            #pragma unroll
            for (int nt = 0; nt < 8; nt++) {
                int col = n_base + nt * 8 + lq;
                bfr[nt][0] = B_s[kq][col];
                bfr[nt][1] = B_s[kq + 4][col];
            }
            #pragma unroll
            for (int mt = 0; mt < 2; mt++)
                #pragma unroll
                for (int nt = 0; nt < 8; nt++)
                    mma_tf32(acc[mt][nt], afr[mt][0], afr[mt][1], afr[mt][2],
                             afr[mt][3], bfr[nt][0], bfr[nt][1]);
        }
    }

    // epilogue: add c, remap r=(t*B+b) -> (b*T+t), store float2 pairs
    #pragma unroll
    for (int nt = 0; nt < 8; nt++) {
        int col = n_base + nt * 8 + 2 * lr;
        float2 cv = *(const float2*)(cvec + v0 + col);
        #pragma unroll
        for (int mt = 0; mt < 2; mt++) {
            #pragma unroll
            for (int h = 0; h < 2; h++) {
                int r = r0 + m_base + mt * 16 + lq + h * 8;
                int orow = (r & 63) * Td + (r >> 6);   // b*T + t
                float2 o;
                o.x = acc[mt][nt][h * 2 + 0] + cv.x;
                o.y = acc[mt][nt][h * 2 + 1] + cv.y;
                *(float2*)(outp + (size_t)orow * Vd + v0 + col) = o;
            }
        }
    }
}

// ---------------------------------------------------------------------------
// K5: in-place log_softmax over rows of 4096. One block (256 thr) per row.
// ---------------------------------------------------------------------------
__global__ void logsoftmax_kernel(float* __restrict__ outp) {
    float* row = outp + (size_t)blockIdx.x * Vd;
    const int tid = threadIdx.x;
    const int lane = tid & 31;
    const int wid = tid >> 5;
    __shared__ float sred[8];

    float4 v[4];
    float mx = -1e30f;
    #pragma unroll
    for (int i = 0; i < 4; i++) {
        v[i] = *(const float4*)(row + (i * 256 + tid) * 4);
        mx = fmaxf(mx, fmaxf(fmaxf(v[i].x, v[i].y), fmaxf(v[i].z, v[i].w)));
    }
    #pragma unroll
    for (int o = 16; o; o >>= 1) mx = fmaxf(mx, __shfl_xor_sync(0xffffffffu, mx, o));
    if (lane == 0) sred[wid] = mx;
    __syncthreads();
    float m2 = sred[lane & 7];
    #pragma unroll
    for (int o = 4; o; o >>= 1) m2 = fmaxf(m2, __shfl_xor_sync(0xffffffffu, m2, o));
    mx = m2;
    __syncthreads();

    float sum = 0.0f;
    #pragma unroll
    for (int i = 0; i < 4; i++) {
        sum += expf(v[i].x - mx) + expf(v[i].y - mx)
             + expf(v[i].z - mx) + expf(v[i].w - mx);
    }
    #pragma unroll
    for (int o = 16; o; o >>= 1) sum += __shfl_xor_sync(0xffffffffu, sum, o);
    if (lane == 0) sred[wid] = sum;
    __syncthreads();
    float s2 = sred[lane & 7];
    #pragma unroll
    for (int o = 4; o; o >>= 1) s2 += __shfl_xor_sync(0xffffffffu, s2, o);

    float lse = mx + logf(s2);
    #pragma unroll
    for (int i = 0; i < 4; i++) {
        v[i].x -= lse; v[i].y -= lse; v[i].z -= lse; v[i].w -= lse;
        *(float4*)(row + (i * 256 + tid) * 4) = v[i];
    }
}

// ---------------------------------------------------------------------------
// K6: hiddens transpose  outh[h, r] = g_hs[r, h]   (r = t*B+b)
// ---------------------------------------------------------------------------
__global__ void transpose_kernel(float* __restrict__ outh) {
    __shared__ float tile[32][33];
    const int h0 = blockIdx.x * 32;
    const int r0 = blockIdx.y * 32;
    const int tx = threadIdx.x;
    const int ty = threadIdx.y;
    #pragma unroll
    for (int i = 0; i < 32; i += 8)
        tile[ty + i][tx] = g_hs[(size_t)(r0 + ty + i) * Hd + h0 + tx];
    __syncthreads();
    #pragma unroll
    for (int i = 0; i < 32; i += 8)
        outh[(size_t)(h0 + ty + i) * BT + r0 + tx] = tile[tx][ty + i];
}

// ---------------------------------------------------------------------------
extern "C" void kernel_launch(void* const* d_in, const int* in_sizes, int n_in,
                              void* d_out, int out_size) {
    const int*   X   = nullptr;
    const float* wxh = nullptr;
    const float* whh = nullptr;
    const float* wvh = nullptr;
    const float* bv  = nullptr;
    const float* cv  = nullptr;

    for (int i = 0; i < n_in; i++) {
        int s = in_sizes[i];
        if (s == BT && !X)            X   = (const int*)d_in[i];
        else if (s == Hd * Hd)        whh = (const float*)d_in[i];
        else if (s == Hd)             bv  = (const float*)d_in[i];
        else if (s == Vd)             cv  = (const float*)d_in[i];
        else if (s == Vd * Hd) {
            if (!wxh) wxh = (const float*)d_in[i];
            else      wvh = (const float*)d_in[i];
        }
    }

    float* outp = (float*)d_out;
    float* outs = outp;                       // (B, T, V) log-probs
    float* outh = outp + (size_t)BT * Vd;     // (H, T, B) hiddens

    // persistent kernel needs 64KB dynamic smem
    static bool attr_done = false;
    if (!attr_done) {
        cudaFuncSetAttribute(rnn_persistent,
                             cudaFuncAttributeMaxDynamicSharedMemorySize,
                             (JPB * Hd + NW * 512) * sizeof(float));
        attr_done = true;
    }

    // 1) embedding gather + bias
    embed_kernel<<<BT, 256>>>(X, wxh, bv);
    // 2) full recurrence in ONE persistent kernel (grid barrier between steps)
    rnn_persistent<<<NBLK, 512, (JPB * Hd + NW * 512) * sizeof(float)>>>(whh);
    // 3) output projection on tf32 tensor cores (writes z with row remap)
    vh_gemm_tf32<<<dim3(Vd / 128, BT / 128), 256>>>(wvh, cv, outs);
    // 4) log_softmax in place
    logsoftmax_kernel<<<BT, 256>>>(outs);
    // 5) hiddens transpose
    transpose_kernel<<<dim3(Hd / 32, BT / 32), dim3(32, 8)>>>(outh);
}

// round 6
// speedup vs baseline: 1.9881x; 1.7146x over previous
#include <cuda_runtime.h>
#include <math.h>
#include <stdint.h>

// Problem constants
#define Hd 1024
#define Vd 4096
#define Bd 64
#define Td 512
#define BT (Bd*Td)       // 32768
#define NBLK 128         // persistent CTAs (one per SM, <=148 => all co-resident)
#define JPB 8            // output columns per CTA (128*8 = 1024)
#define NW 16            // warps per CTA in persistent kernel
#define WST 1028         // Wsl row stride (floats): 16B-aligned, bank-spread

// smem float offsets
#define SM_W    0                       // Wsl: 8 * 1028 = 8224 floats
#define SM_H    8224                    // h_s: 2 * 2048 float4 = 16384 floats
#define SM_RED  (8224 + 16384)          // red: 16 * 512 = 8192 floats
#define SM_TOT  (8224 + 16384 + 8192)   // 32800 floats = 131200 B

// Scratch (device globals; no runtime allocation)
__device__ float g_abase[(size_t)BT*Hd];   // (t,b,h) pre-activation x_emb + b
__device__ float g_hs[(size_t)BT*Hd];      // (t,b,h) hidden states
__device__ unsigned g_cnt_grp[8*32];       // group counters (128B apart)
__device__ unsigned g_cnt_root;
__device__ unsigned g_gen;

// ---------------------------------------------------------------------------
// K1: embedding gather + bias  a_base[(t*B+b), :] = wxh[X[b,t], :] + bvec
// ---------------------------------------------------------------------------
__global__ void embed_kernel(const int* __restrict__ X,
                             const float* __restrict__ wxh,
                             const float* __restrict__ bvec) {
    int r = blockIdx.x;            // r = t*B + b
    int t = r >> 6;
    int b = r & 63;
    int row = X[b * Td + t];
    const float4* src = (const float4*)(wxh + (size_t)row * Hd);
    const float4* bb  = (const float4*)bvec;
    float4* dst = (float4*)(g_abase + (size_t)r * Hd);
    int i = threadIdx.x;           // 256 = H/4
    float4 v = src[i];
    float4 w = bb[i];
    v.x += w.x; v.y += w.y; v.z += w.z; v.w += w.w;
    dst[i] = v;
}

// ---------------------------------------------------------------------------
// Two-level grid barrier: 8 groups of 16 CTAs (group counters on separate
// 128B lines) + root counter; release via monotonic generation. All NBLK
// CTAs co-resident (128 CTAs, 1/SM). Deterministic, graph-replay safe
// (counters self-reset; gen only compared for equality).
// ---------------------------------------------------------------------------
__device__ __forceinline__ void grid_barrier(int tid, int bid) {
    __syncthreads();
    if (tid == 0) {
        unsigned gen = *(volatile unsigned*)&g_gen;   // read BEFORE arrive
        __threadfence();                              // publish CTA's writes
        int grp = bid >> 4;
        unsigned p = atomicAdd(&g_cnt_grp[grp * 32], 1u);
        if (p == 15u) {
            unsigned r = atomicAdd(&g_cnt_root, 1u);
            if (r == 7u) {
                atomicExch(&g_cnt_root, 0u);
                #pragma unroll
                for (int i = 0; i < 8; i++) atomicExch(&g_cnt_grp[i * 32], 0u);
                __threadfence();
                atomicExch(&g_gen, gen + 1u);         // release
            } else {
                while (*(volatile unsigned*)&g_gen == gen) { }
            }
        } else {
            while (*(volatile unsigned*)&g_gen == gen) { }
        }
        __threadfence();                              // acquire
    }
    __syncthreads();
}

// ---------------------------------------------------------------------------
// K2: persistent recurrence. CTA owns 8 output cols; W slice (8x1024) in smem
// all 512 steps. Per step: h_{t-1} staged into smem in 8 double-buffered
// 64x128 chunks (coalesced LDG.128 -> XOR-swizzled STS); 16 warps split each
// chunk's K 16 ways; thread tile 4b x 4j from smem; cross-warp smem reduce,
// tanh fused, two-level grid barrier between steps.
// ---------------------------------------------------------------------------
__global__ void __launch_bounds__(512, 1)
rnn_persistent(const float* __restrict__ whh) {
    extern __shared__ float dsm[];
    float*  Wsl = dsm + SM_W;
    float4* hs4 = (float4*)(dsm + SM_H);    // [2][64][32] float4, XOR-swizzled
    float*  red = dsm + SM_RED;             // [16][512]

    const int bid = blockIdx.x;     // 0..127
    const int j0  = bid * JPB;
    const int tid = threadIdx.x;
    const int w   = tid >> 5;       // warp 0..15
    const int ln  = tid & 31;

    // Load W_hh slice rows j0..j0+7 into stride-1028 smem rows (coalesced)
    {
        const float4* wsrc = (const float4*)(whh + (size_t)j0 * Hd);
        for (int idx = tid; idx < 2048; idx += 512) {
            int rw = idx >> 8, c4 = idx & 255;
            *(float4*)&Wsl[rw * WST + c4 * 4] = wsrc[rw * 256 + c4];
        }
    }

    // h_0 = tanh(a_base[0]) for this CTA's columns (1 elem/thread)
    {
        int b = tid >> 3, j = tid & 7;
        g_hs[(size_t)b * Hd + j0 + j] = tanhf(g_abase[(size_t)b * Hd + j0 + j]);
    }

    // FMA-phase geometry
    const int brow = (ln >> 1) * 4;     // 4 consecutive batch rows
    const int jcol = (ln & 1) * 4;      // 0 or 4
    // staging geometry: thread q-th load covers global f4 index tid + q*512
    int srow[4], sphys[4];
    #pragma unroll
    for (int q = 0; q < 4; q++) {
        int gi = tid + q * 512;
        int r = gi >> 5, u = gi & 31;
        srow[q]  = r;
        sphys[q] = r * 32 + (u ^ (r & 31));
    }

    for (int t = 1; t < Td; t++) {
        grid_barrier(tid, bid);   // h_{t-1} visible; also guards red & hs4 reuse

        const float* hrow = g_hs + (size_t)(t - 1) * (Bd * Hd);

        float acc[4][4];
        #pragma unroll
        for (int i = 0; i < 4; i++)
            #pragma unroll
            for (int m = 0; m < 4; m++) acc[i][m] = 0.0f;

        // preload chunk 0
        {
            float4 pf[4];
            #pragma unroll
            for (int q = 0; q < 4; q++)
                pf[q] = *(const float4*)(hrow + (size_t)srow[q] * Hd + ((tid + q*512) & 31) * 4);
            #pragma unroll
            for (int q = 0; q < 4; q++) hs4[sphys[q]] = pf[q];
        }
        __syncthreads();

        #pragma unroll 1
        for (int c = 0; c < 8; c++) {
            const int cur = c & 1;
            float4 pf[4];
            if (c < 7) {
                const float* hc = hrow + (c + 1) * 128;
                #pragma unroll
                for (int q = 0; q < 4; q++)
                    pf[q] = *(const float4*)(hc + (size_t)srow[q] * Hd + ((tid + q*512) & 31) * 4);
            }

            // compute chunk c: warp w covers k = c*128 + w*8 .. +8 (2 groups)
            const float4* hb = hs4 + cur * 2048;
            #pragma unroll
            for (int g = 0; g < 2; g++) {
                const int u0 = w * 2 + g;
                float4 h4[4];
                #pragma unroll
                for (int i = 0; i < 4; i++) {
                    int r = brow + i;
                    h4[i] = hb[r * 32 + (u0 ^ (r & 31))];
                }
                const int kabs = c * 128 + w * 8 + g * 4;
                float4 w4[4];
                #pragma unroll
                for (int m = 0; m < 4; m++)
                    w4[m] = *(const float4*)&Wsl[(jcol + m) * WST + kabs];
                #pragma unroll
                for (int i = 0; i < 4; i++) {
                    float4 hv = h4[i];
                    #pragma unroll
                    for (int m = 0; m < 4; m++) {
                        acc[i][m] = fmaf(hv.x, w4[m].x, acc[i][m]);
                        acc[i][m] = fmaf(hv.y, w4[m].y, acc[i][m]);
                        acc[i][m] = fmaf(hv.z, w4[m].z, acc[i][m]);
                        acc[i][m] = fmaf(hv.w, w4[m].w, acc[i][m]);
                    }
                }
            }

            if (c < 7) {
                float4* hn = hs4 + (cur ^ 1) * 2048;
                #pragma unroll
                for (int q = 0; q < 4; q++) hn[sphys[q]] = pf[q];
            }
            __syncthreads();
        }

        // store partials: red[w*512 + ln*4 + i*128 + m]  (STS.128 conflict-free)
        {
            float* myred = &red[w * 512 + ln * 4];
            #pragma unroll
            for (int i = 0; i < 4; i++)
                *(float4*)&myred[i * 128] =
                    make_float4(acc[i][0], acc[i][1], acc[i][2], acc[i][3]);
        }
        __syncthreads();

        // reduce 16 warps, add a_base, tanh, write h_t (1 output/thread)
        {
            int b = tid >> 3, j = tid & 7;
            int idx = (b & 3) * 128 + ((b >> 2) * 2 + (j >> 2)) * 4 + (j & 3);
            float s = g_abase[(size_t)t * (Bd * Hd) + (size_t)b * Hd + j0 + j];
            #pragma unroll
            for (int ww = 0; ww < NW; ww++)
                s += red[ww * 512 + idx];
            g_hs[(size_t)t * (Bd * Hd) + (size_t)b * Hd + j0 + j] = tanhf(s);
        }
        // next grid_barrier's __syncthreads guards red/hs4 before overwrite
    }
}

// ---------------------------------------------------------------------------
// K4: output GEMM on tf32 tensor cores.
// z[r, v] = sum_k Hs[r,k] * Wvh[v,k] + c[v], row remap r=(t*B+b) -> (b*T+t).
// BM=128, BN=128, BK=16. 8 warps as 4(m) x 2(n); warp tile 32x64 =
// 2 x 8 tiles of m16n8k8. A row-major, B col-major (wvh rows ARE B columns).
// ---------------------------------------------------------------------------
__device__ __forceinline__ uint32_t f2tf32(float x) {
    uint32_t r;
    asm("cvt.rna.tf32.f32 %0, %1;" : "=r"(r) : "f"(x));
    return r;
}
__device__ __forceinline__ void mma_tf32(float c[4], uint32_t a0, uint32_t a1,
                                         uint32_t a2, uint32_t a3,
                                         uint32_t b0, uint32_t b1) {
    asm volatile(
        "mma.sync.aligned.m16n8k8.row.col.f32.tf32.tf32.f32 "
        "{%0,%1,%2,%3}, {%4,%5,%6,%7}, {%8,%9}, {%0,%1,%2,%3};"
        : "+f"(c[0]), "+f"(c[1]), "+f"(c[2]), "+f"(c[3])
        : "r"(a0), "r"(a1), "r"(a2), "r"(a3), "r"(b0), "r"(b1));
}

#define LDA 136   // pad: conflict-free fragment loads

__global__ void __launch_bounds__(256, 1)
vh_gemm_tf32(const float* __restrict__ wvh,
             const float* __restrict__ cvec,
             float* __restrict__ outp) {
    __shared__ uint32_t A_s[16][LDA];
    __shared__ uint32_t B_s[16][LDA];
    const int v0 = blockIdx.x * 128;
    const int r0 = blockIdx.y * 128;
    const int tid  = threadIdx.x;
    const int warp = tid >> 5;
    const int lane = tid & 31;
    const int warp_m = warp & 3;        // 4 m-warps
    const int warp_n = warp >> 2;       // 2 n-warps
    const int m_base = warp_m * 32;
    const int n_base = warp_n * 64;
    const int lq = lane >> 2;           // 0..7
    const int lr = lane & 3;            // 0..3

    float acc[2][8][4];
    #pragma unroll
    for (int mt = 0; mt < 2; mt++)
        #pragma unroll
        for (int nt = 0; nt < 8; nt++)
            #pragma unroll
            for (int e = 0; e < 4; e++) acc[mt][nt][e] = 0.0f;

    const int lrow = tid >> 2;          // 0..63
    const int lk4  = (tid & 3) * 4;

    for (int kc = 0; kc < 64; ++kc) {
        int k0 = kc * 16;
        float4 a0 = *(const float4*)(g_hs + (size_t)(r0 + lrow) * Hd + k0 + lk4);
        float4 a1 = *(const float4*)(g_hs + (size_t)(r0 + lrow + 64) * Hd + k0 + lk4);
        float4 b0 = *(const float4*)(wvh + (size_t)(v0 + lrow) * Hd + k0 + lk4);
        float4 b1 = *(const float4*)(wvh + (size_t)(v0 + lrow + 64) * Hd + k0 + lk4);
        __syncthreads();
        A_s[lk4 + 0][lrow] = f2tf32(a0.x); A_s[lk4 + 1][lrow] = f2tf32(a0.y);
        A_s[lk4 + 2][lrow] = f2tf32(a0.z); A_s[lk4 + 3][lrow] = f2tf32(a0.w);
        A_s[lk4 + 0][lrow + 64] = f2tf32(a1.x); A_s[lk4 + 1][lrow + 64] = f2tf32(a1.y);
        A_s[lk4 + 2][lrow + 64] = f2tf32(a1.z); A_s[lk4 + 3][lrow + 64] = f2tf32(a1.w);
        B_s[lk4 + 0][lrow] = f2tf32(b0.x); B_s[lk4 + 1][lrow] = f2tf32(b0.y);
        B_s[lk4 + 2][lrow] = f2tf32(b0.z); B_s[lk4 + 3][lrow] = f2tf32(b0.w);
        B_s[lk4 + 0][lrow + 64] = f2tf32(b1.x); B_s[lk4 + 1][lrow + 64] = f2tf32(b1.y);
        B_s[lk4 + 2][lrow + 64] = f2tf32(b1.z); B_s[lk4 + 3][lrow + 64] = f2tf32(b1.w);
        __syncthreads();

        #pragma unroll
        for (int ks = 0; ks < 2; ks++) {
            int kq = ks * 8 + lr;
            uint32_t afr[2][4];
            #pragma unroll
            for (int mt = 0; mt < 2; mt++) {
                int row = m_base + mt * 16 + lq;
                afr[mt][0] = A_s[kq][row];
                afr[mt][1] = A_s[kq][row + 8];
                afr[mt][2] = A_s[kq + 4][row];
                afr[mt][3] = A_s[kq + 4][row + 8];
            }
            uint32_t bfr[8][2];
            #pragma unroll
            for (int nt = 0; nt < 8; nt++) {
                int col = n_base + nt * 8 + lq;
                bfr[nt][0] = B_s[kq][col];
                bfr[nt][1] = B_s[kq + 4][col];
            }
            #pragma unroll
            for (int mt = 0; mt < 2; mt++)
                #pragma unroll
                for (int nt = 0; nt < 8; nt++)
                    mma_tf32(acc[mt][nt], afr[mt][0], afr[mt][1], afr[mt][2],
                             afr[mt][3], bfr[nt][0], bfr[nt][1]);
        }
    }

    // epilogue: add c, remap r=(t*B+b) -> (b*T+t), store float2 pairs
    #pragma unroll
    for (int nt = 0; nt < 8; nt++) {
        int col = n_base + nt * 8 + 2 * lr;
        float2 cv = *(const float2*)(cvec + v0 + col);
        #pragma unroll
        for (int mt = 0; mt < 2; mt++) {
            #pragma unroll
            for (int h = 0; h < 2; h++) {
                int r = r0 + m_base + mt * 16 + lq + h * 8;
                int orow = (r & 63) * Td + (r >> 6);   // b*T + t
                float2 o;
                o.x = acc[mt][nt][h * 2 + 0] + cv.x;
                o.y = acc[mt][nt][h * 2 + 1] + cv.y;
                *(float2*)(outp + (size_t)orow * Vd + v0 + col) = o;
            }
        }
    }
}

// ---------------------------------------------------------------------------
// K5: in-place log_softmax over rows of 4096. One block (256 thr) per row.
// ---------------------------------------------------------------------------
__global__ void logsoftmax_kernel(float* __restrict__ outp) {
    float* row = outp + (size_t)blockIdx.x * Vd;
    const int tid = threadIdx.x;
    const int lane = tid & 31;
    const int wid = tid >> 5;
    __shared__ float sred[8];

    float4 v[4];
    float mx = -1e30f;
    #pragma unroll
    for (int i = 0; i < 4; i++) {
        v[i] = *(const float4*)(row + (i * 256 + tid) * 4);
        mx = fmaxf(mx, fmaxf(fmaxf(v[i].x, v[i].y), fmaxf(v[i].z, v[i].w)));
    }
    #pragma unroll
    for (int o = 16; o; o >>= 1) mx = fmaxf(mx, __shfl_xor_sync(0xffffffffu, mx, o));
    if (lane == 0) sred[wid] = mx;
    __syncthreads();
    float m2 = sred[lane & 7];
    #pragma unroll
    for (int o = 4; o; o >>= 1) m2 = fmaxf(m2, __shfl_xor_sync(0xffffffffu, m2, o));
    mx = m2;
    __syncthreads();

    float sum = 0.0f;
    #pragma unroll
    for (int i = 0; i < 4; i++) {
        sum += expf(v[i].x - mx) + expf(v[i].y - mx)
             + expf(v[i].z - mx) + expf(v[i].w - mx);
    }
    #pragma unroll
    for (int o = 16; o; o >>= 1) sum += __shfl_xor_sync(0xffffffffu, sum, o);
    if (lane == 0) sred[wid] = sum;
    __syncthreads();
    float s2 = sred[lane & 7];
    #pragma unroll
    for (int o = 4; o; o >>= 1) s2 += __shfl_xor_sync(0xffffffffu, s2, o);

    float lse = mx + logf(s2);
    #pragma unroll
    for (int i = 0; i < 4; i++) {
        v[i].x -= lse; v[i].y -= lse; v[i].z -= lse; v[i].w -= lse;
        *(float4*)(row + (i * 256 + tid) * 4) = v[i];
    }
}

// ---------------------------------------------------------------------------
// K6: hiddens transpose  outh[h, r] = g_hs[r, h]   (r = t*B+b)
// ---------------------------------------------------------------------------
__global__ void transpose_kernel(float* __restrict__ outh) {
    __shared__ float tile[32][33];
    const int h0 = blockIdx.x * 32;
    const int r0 = blockIdx.y * 32;
    const int tx = threadIdx.x;
    const int ty = threadIdx.y;
    #pragma unroll
    for (int i = 0; i < 32; i += 8)
        tile[ty + i][tx] = g_hs[(size_t)(r0 + ty + i) * Hd + h0 + tx];
    __syncthreads();
    #pragma unroll
    for (int i = 0; i < 32; i += 8)
        outh[(size_t)(h0 + ty + i) * BT + r0 + tx] = tile[tx][ty + i];
}

// ---------------------------------------------------------------------------
extern "C" void kernel_launch(void* const* d_in, const int* in_sizes, int n_in,
                              void* d_out, int out_size) {
    const int*   X   = nullptr;
    const float* wxh = nullptr;
    const float* whh = nullptr;
    const float* wvh = nullptr;
    const float* bv  = nullptr;
    const float* cv  = nullptr;

    for (int i = 0; i < n_in; i++) {
        int s = in_sizes[i];
        if (s == BT && !X)            X   = (const int*)d_in[i];
        else if (s == Hd * Hd)        whh = (const float*)d_in[i];
        else if (s == Hd)             bv  = (const float*)d_in[i];
        else if (s == Vd)             cv  = (const float*)d_in[i];
        else if (s == Vd * Hd) {
            if (!wxh) wxh = (const float*)d_in[i];
            else      wvh = (const float*)d_in[i];
        }
    }

    float* outp = (float*)d_out;
    float* outs = outp;                       // (B, T, V) log-probs
    float* outh = outp + (size_t)BT * Vd;     // (H, T, B) hiddens

    // persistent kernel needs 131,200 B dynamic smem (idempotent host call)
    cudaFuncSetAttribute(rnn_persistent,
                         cudaFuncAttributeMaxDynamicSharedMemorySize,
                         SM_TOT * (int)sizeof(float));

    // 1) embedding gather + bias
    embed_kernel<<<BT, 256>>>(X, wxh, bv);
    // 2) full recurrence in ONE persistent kernel (grid barrier between steps)
    rnn_persistent<<<NBLK, 512, SM_TOT * (int)sizeof(float)>>>(whh);
    // 3) output projection on tf32 tensor cores (writes z with row remap)
    vh_gemm_tf32<<<dim3(Vd / 128, BT / 128), 256>>>(wvh, cv, outs);
    // 4) log_softmax in place
    logsoftmax_kernel<<<BT, 256>>>(outs);
    // 5) hiddens transpose
    transpose_kernel<<<dim3(Hd / 32, BT / 32), dim3(32, 8)>>>(outh);
}

// round 7
// speedup vs baseline: 2.1410x; 1.0769x over previous
#include <cuda_runtime.h>
#include <math.h>
#include <stdint.h>

// Problem constants
#define Hd 1024
#define Vd 4096
#define Bd 64
#define Td 512
#define BT (Bd*Td)       // 32768
#define NBLK 128         // persistent CTAs (one per SM, <=148 => all co-resident)
#define JPB 8            // output columns per CTA (128*8 = 1024)
#define NW 16            // warps per CTA in persistent kernel
#define WST 1028         // Wsl row stride (floats): 16B-aligned, bank-spread

// smem float offsets (persistent kernel)
#define SM_W    0                        // Wsl: 8 * 1028 = 8224 floats
#define SM_H    8224                     // h_s: 2 buf * 64 rows * 256 = 32768 floats
#define SM_RED  (8224 + 32768)           // red: 16 * 512 = 8192 floats
#define SM_TOT  (8224 + 32768 + 8192)    // 49184 floats = 196736 B

// Scratch (device globals; no runtime allocation)
__device__ float g_abase[(size_t)BT*Hd];   // (t,b,h) pre-activation x_emb + b
__device__ float g_hs[(size_t)BT*Hd];      // (t,b,h) hidden states
__device__ unsigned g_cnt_grp[8*32];       // group counters (128B apart)
__device__ unsigned g_cnt_root;
__device__ unsigned g_gen;

// ---------------------------------------------------------------------------
// K1: embedding gather + bias  a_base[(t*B+b), :] = wxh[X[b,t], :] + bvec
// ---------------------------------------------------------------------------
__global__ void embed_kernel(const int* __restrict__ X,
                             const float* __restrict__ wxh,
                             const float* __restrict__ bvec) {
    int r = blockIdx.x;            // r = t*B + b
    int t = r >> 6;
    int b = r & 63;
    int row = X[b * Td + t];
    const float4* src = (const float4*)(wxh + (size_t)row * Hd);
    const float4* bb  = (const float4*)bvec;
    float4* dst = (float4*)(g_abase + (size_t)r * Hd);
    int i = threadIdx.x;           // 256 = H/4
    float4 v = src[i];
    float4 w = bb[i];
    v.x += w.x; v.y += w.y; v.z += w.z; v.w += w.w;
    dst[i] = v;
}

// ---------------------------------------------------------------------------
// Two-level grid barrier: 8 groups of 16 CTAs (group counters on separate
// 128B lines) + root; release via monotonic generation. All NBLK CTAs
// co-resident. Deterministic, graph-replay safe (self-resetting counters).
// ---------------------------------------------------------------------------
__device__ __forceinline__ void grid_barrier(int tid, int bid) {
    __syncthreads();
    if (tid == 0) {
        unsigned gen = *(volatile unsigned*)&g_gen;   // read BEFORE arrive
        __threadfence();                              // publish CTA's writes
        int grp = bid >> 4;
        unsigned p = atomicAdd(&g_cnt_grp[grp * 32], 1u);
        if (p == 15u) {
            unsigned r = atomicAdd(&g_cnt_root, 1u);
            if (r == 7u) {
                atomicExch(&g_cnt_root, 0u);
                #pragma unroll
                for (int i = 0; i < 8; i++) atomicExch(&g_cnt_grp[i * 32], 0u);
                __threadfence();
                atomicExch(&g_gen, gen + 1u);         // release
            } else {
                while (*(volatile unsigned*)&g_gen == gen) { }
            }
        } else {
            while (*(volatile unsigned*)&g_gen == gen) { }
        }
        __threadfence();                              // acquire
    }
    __syncthreads();
}

// ---------------------------------------------------------------------------
// K2: persistent recurrence. CTA owns 8 output cols; W slice (8x1024) in smem
// all 512 steps. Per step: h_{t-1} staged in 4 double-buffered 64x256 chunks
// (64KB; coalesced LDG.128 -> swizzled STS.128); 16 warps split each chunk's
// K 16 ways (4 float4-groups each); thread tile 4b x 4j; cross-warp smem
// reduce, tanh fused, two-level grid barrier between steps.
// Swizzle: phys_f4 = r*64 + (u ^ ((r>>2)&7)).
// ---------------------------------------------------------------------------
__global__ void __launch_bounds__(512, 1)
rnn_persistent(const float* __restrict__ whh) {
    extern __shared__ float dsm[];
    float*  Wsl = dsm + SM_W;
    float4* hs4 = (float4*)(dsm + SM_H);    // [2][64][64] float4 (swizzled)
    float*  red = dsm + SM_RED;             // [16][512]

    const int bid = blockIdx.x;     // 0..127
    const int j0  = bid * JPB;
    const int tid = threadIdx.x;
    const int w   = tid >> 5;       // warp 0..15
    const int ln  = tid & 31;

    // Load W_hh slice rows j0..j0+7 into stride-1028 smem rows (coalesced)
    {
        const float4* wsrc = (const float4*)(whh + (size_t)j0 * Hd);
        for (int idx = tid; idx < 2048; idx += 512) {
            int rw = idx >> 8, c4 = idx & 255;
            *(float4*)&Wsl[rw * WST + c4 * 4] = wsrc[rw * 256 + c4];
        }
    }

    // h_0 = tanh(a_base[0]) for this CTA's columns (1 elem/thread)
    {
        int b = tid >> 3, j = tid & 7;
        g_hs[(size_t)b * Hd + j0 + j] = tanhf(g_abase[(size_t)b * Hd + j0 + j]);
    }

    // FMA-phase geometry
    const int brow = (ln >> 1) * 4;     // 4 consecutive batch rows
    const int jcol = (ln & 1) * 4;      // 0 or 4
    const int hkey = (brow >> 2) & 7;   // swizzle key (constant over i, i<4)

    // staging geometry: thread's q-th f4 covers chunk-local f4 index tid+q*512
    int srow[8], sphys[8], scol[8];
    #pragma unroll
    for (int q = 0; q < 8; q++) {
        int gi = tid + q * 512;          // 0..4095
        int r = gi >> 6, u = gi & 63;
        srow[q]  = r;
        scol[q]  = u;
        sphys[q] = r * 64 + (u ^ ((r >> 2) & 7));
    }

    for (int t = 1; t < Td; t++) {
        grid_barrier(tid, bid);   // h_{t-1} visible; also guards red & hs4 reuse

        const float* hrow = g_hs + (size_t)(t - 1) * (Bd * Hd);

        float acc[4][4];
        #pragma unroll
        for (int i = 0; i < 4; i++)
            #pragma unroll
            for (int m = 0; m < 4; m++) acc[i][m] = 0.0f;

        // preload chunk 0 (k = 0..255)
        {
            float4 pf[8];
            #pragma unroll
            for (int q = 0; q < 8; q++)
                pf[q] = *(const float4*)(hrow + (size_t)srow[q] * Hd + scol[q] * 4);
            #pragma unroll
            for (int q = 0; q < 8; q++) hs4[sphys[q]] = pf[q];
        }
        __syncthreads();

        #pragma unroll 1
        for (int c = 0; c < 4; c++) {
            const int cur = c & 1;
            float4 pf[8];
            if (c < 3) {
                const float* hc = hrow + (c + 1) * 256;
                #pragma unroll
                for (int q = 0; q < 8; q++)
                    pf[q] = *(const float4*)(hc + (size_t)srow[q] * Hd + scol[q] * 4);
            }

            // compute chunk c: warp w covers k = c*256 + w*16 .. +16 (4 groups)
            const float4* hb = hs4 + cur * 4096;
            #pragma unroll
            for (int g = 0; g < 4; g++) {
                const int u0 = w * 4 + g;
                float4 h4[4];
                #pragma unroll
                for (int i = 0; i < 4; i++)
                    h4[i] = hb[(brow + i) * 64 + (u0 ^ hkey)];
                const int kabs = c * 256 + w * 16 + g * 4;
                float4 w4[4];
                #pragma unroll
                for (int m = 0; m < 4; m++)
                    w4[m] = *(const float4*)&Wsl[(jcol + m) * WST + kabs];
                #pragma unroll
                for (int i = 0; i < 4; i++) {
                    float4 hv = h4[i];
                    #pragma unroll
                    for (int m = 0; m < 4; m++) {
                        acc[i][m] = fmaf(hv.x, w4[m].x, acc[i][m]);
                        acc[i][m] = fmaf(hv.y, w4[m].y, acc[i][m]);
                        acc[i][m] = fmaf(hv.z, w4[m].z, acc[i][m]);
                        acc[i][m] = fmaf(hv.w, w4[m].w, acc[i][m]);
                    }
                }
            }

            if (c < 3) {
                float4* hn = hs4 + (cur ^ 1) * 4096;
                #pragma unroll
                for (int q = 0; q < 8; q++) hn[sphys[q]] = pf[q];
            }
            __syncthreads();
        }

        // store partials: red[w*512 + ln*4 + i*128 + m]  (STS.128 conflict-free)
        {
            float* myred = &red[w * 512 + ln * 4];
            #pragma unroll
            for (int i = 0; i < 4; i++)
                *(float4*)&myred[i * 128] =
                    make_float4(acc[i][0], acc[i][1], acc[i][2], acc[i][3]);
        }
        __syncthreads();

        // reduce 16 warps, add a_base, tanh, write h_t (1 output/thread)
        {
            int b = tid >> 3, j = tid & 7;
            int idx = (b & 3) * 128 + ((b >> 2) * 2 + (j >> 2)) * 4 + (j & 3);
            float s = g_abase[(size_t)t * (Bd * Hd) + (size_t)b * Hd + j0 + j];
            #pragma unroll
            for (int ww = 0; ww < NW; ww++)
                s += red[ww * 512 + idx];
            g_hs[(size_t)t * (Bd * Hd) + (size_t)b * Hd + j0 + j] = tanhf(s);
        }
        // next grid_barrier's __syncthreads guards red/hs4 before overwrite
    }
}

// ---------------------------------------------------------------------------
// K4: output GEMM on tf32 tensor cores.
// z[r, v] = sum_k Hs[r,k] * Wvh[v,k] + c[v], row remap r=(t*B+b) -> (b*T+t).
// BM=128, BN=128, BK=16. 8 warps as 4(m) x 2(n); warp tile 32x64 =
// 2 x 8 tiles of m16n8k8. A row-major, B col-major (wvh rows ARE B columns).
// ---------------------------------------------------------------------------
__device__ __forceinline__ uint32_t f2tf32(float x) {
    uint32_t r;
    asm("cvt.rna.tf32.f32 %0, %1;" : "=r"(r) : "f"(x));
    return r;
}
__device__ __forceinline__ void mma_tf32(float c[4], uint32_t a0, uint32_t a1,
                                         uint32_t a2, uint32_t a3,
                                         uint32_t b0, uint32_t b1) {
    asm volatile(
        "mma.sync.aligned.m16n8k8.row.col.f32.tf32.tf32.f32 "
        "{%0,%1,%2,%3}, {%4,%5,%6,%7}, {%8,%9}, {%0,%1,%2,%3};"
        : "+f"(c[0]), "+f"(c[1]), "+f"(c[2]), "+f"(c[3])
        : "r"(a0), "r"(a1), "r"(a2), "r"(a3), "r"(b0), "r"(b1));
}

#define LDA 136   // pad: conflict-free fragment loads

__global__ void __launch_bounds__(256, 1)
vh_gemm_tf32(const float* __restrict__ wvh,
             const float* __restrict__ cvec,
             float* __restrict__ outp) {
    __shared__ uint32_t A_s[16][LDA];
    __shared__ uint32_t B_s[16][LDA];
    const int v0 = blockIdx.x * 128;
    const int r0 = blockIdx.y * 128;
    const int tid  = threadIdx.x;
    const int warp = tid >> 5;
    const int lane = tid & 31;
    const int warp_m = warp & 3;        // 4 m-warps
    const int warp_n = warp >> 2;       // 2 n-warps
    const int m_base = warp_m * 32;
    const int n_base = warp_n * 64;
    const int lq = lane >> 2;           // 0..7
    const int lr = lane & 3;            // 0..3

    float acc[2][8][4];
    #pragma unroll
    for (int mt = 0; mt < 2; mt++)
        #pragma unroll
        for (int nt = 0; nt < 8; nt++)
            #pragma unroll
            for (int e = 0; e < 4; e++) acc[mt][nt][e] = 0.0f;

    const int lrow = tid >> 2;          // 0..63
    const int lk4  = (tid & 3) * 4;

    for (int kc = 0; kc < 64; ++kc) {
        int k0 = kc * 16;
        float4 a0 = *(const float4*)(g_hs + (size_t)(r0 + lrow) * Hd + k0 + lk4);
        float4 a1 = *(const float4*)(g_hs + (size_t)(r0 + lrow + 64) * Hd + k0 + lk4);
        float4 b0 = *(const float4*)(wvh + (size_t)(v0 + lrow) * Hd + k0 + lk4);
        float4 b1 = *(const float4*)(wvh + (size_t)(v0 + lrow + 64) * Hd + k0 + lk4);
        __syncthreads();
        A_s[lk4 + 0][lrow] = f2tf32(a0.x); A_s[lk4 + 1][lrow] = f2tf32(a0.y);
        A_s[lk4 + 2][lrow] = f2tf32(a0.z); A_s[lk4 + 3][lrow] = f2tf32(a0.w);
        A_s[lk4 + 0][lrow + 64] = f2tf32(a1.x); A_s[lk4 + 1][lrow + 64] = f2tf32(a1.y);
        A_s[lk4 + 2][lrow + 64] = f2tf32(a1.z); A_s[lk4 + 3][lrow + 64] = f2tf32(a1.w);
        B_s[lk4 + 0][lrow] = f2tf32(b0.x); B_s[lk4 + 1][lrow] = f2tf32(b0.y);
        B_s[lk4 + 2][lrow] = f2tf32(b0.z); B_s[lk4 + 3][lrow] = f2tf32(b0.w);
        B_s[lk4 + 0][lrow + 64] = f2tf32(b1.x); B_s[lk4 + 1][lrow + 64] = f2tf32(b1.y);
        B_s[lk4 + 2][lrow + 64] = f2tf32(b1.z); B_s[lk4 + 3][lrow + 64] = f2tf32(b1.w);
        __syncthreads();

        #pragma unroll
        for (int ks = 0; ks < 2; ks++) {
            int kq = ks * 8 + lr;
            uint32_t afr[2][4];
            #pragma unroll
            for (int mt = 0; mt < 2; mt++) {
                int row = m_base + mt * 16 + lq;
                afr[mt][0] = A_s[kq][row];
                afr[mt][1] = A_s[kq][row + 8];
                afr[mt][2] = A_s[kq + 4][row];
                afr[mt][3] = A_s[kq + 4][row + 8];
            }
            uint32_t bfr[8][2];
            #pragma unroll
            for (int nt = 0; nt < 8; nt++) {
                int col = n_base + nt * 8 + lq;
                bfr[nt][0] = B_s[kq][col];
                bfr[nt][1] = B_s[kq + 4][col];
            }
            #pragma unroll
            for (int mt = 0; mt < 2; mt++)
                #pragma unroll
                for (int nt = 0; nt < 8; nt++)
                    mma_tf32(acc[mt][nt], afr[mt][0], afr[mt][1], afr[mt][2],
                             afr[mt][3], bfr[nt][0], bfr[nt][1]);
        }
    }

    // epilogue: add c, remap r=(t*B+b) -> (b*T+t), store float2 pairs
    #pragma unroll
    for (int nt = 0; nt < 8; nt++) {
        int col = n_base + nt * 8 + 2 * lr;
        float2 cv = *(const float2*)(cvec + v0 + col);
        #pragma unroll
        for (int mt = 0; mt < 2; mt++) {
            #pragma unroll
            for (int h = 0; h < 2; h++) {
                int r = r0 + m_base + mt * 16 + lq + h * 8;
                int orow = (r & 63) * Td + (r >> 6);   // b*T + t
                float2 o;
                o.x = acc[mt][nt][h * 2 + 0] + cv.x;
                o.y = acc[mt][nt][h * 2 + 1] + cv.y;
                *(float2*)(outp + (size_t)orow * Vd + v0 + col) = o;
            }
        }
    }
}

// ---------------------------------------------------------------------------
// K5: in-place log_softmax over rows of 4096. One block (256 thr) per row.
// ---------------------------------------------------------------------------
__global__ void logsoftmax_kernel(float* __restrict__ outp) {
    float* row = outp + (size_t)blockIdx.x * Vd;
    const int tid = threadIdx.x;
    const int lane = tid & 31;
    const int wid = tid >> 5;
    __shared__ float sred[8];

    float4 v[4];
    float mx = -1e30f;
    #pragma unroll
    for (int i = 0; i < 4; i++) {
        v[i] = *(const float4*)(row + (i * 256 + tid) * 4);
        mx = fmaxf(mx, fmaxf(fmaxf(v[i].x, v[i].y), fmaxf(v[i].z, v[i].w)));
    }
    #pragma unroll
    for (int o = 16; o; o >>= 1) mx = fmaxf(mx, __shfl_xor_sync(0xffffffffu, mx, o));
    if (lane == 0) sred[wid] = mx;
    __syncthreads();
    float m2 = sred[lane & 7];
    #pragma unroll
    for (int o = 4; o; o >>= 1) m2 = fmaxf(m2, __shfl_xor_sync(0xffffffffu, m2, o));
    mx = m2;
    __syncthreads();

    float sum = 0.0f;
    #pragma unroll
    for (int i = 0; i < 4; i++) {
        sum += expf(v[i].x - mx) + expf(v[i].y - mx)
             + expf(v[i].z - mx) + expf(v[i].w - mx);
    }
    #pragma unroll
    for (int o = 16; o; o >>= 1) sum += __shfl_xor_sync(0xffffffffu, sum, o);
    if (lane == 0) sred[wid] = sum;
    __syncthreads();
    float s2 = sred[lane & 7];
    #pragma unroll
    for (int o = 4; o; o >>= 1) s2 += __shfl_xor_sync(0xffffffffu, s2, o);

    float lse = mx + logf(s2);
    #pragma unroll
    for (int i = 0; i < 4; i++) {
        v[i].x -= lse; v[i].y -= lse; v[i].z -= lse; v[i].w -= lse;
        *(float4*)(row + (i * 256 + tid) * 4) = v[i];
    }
}

// ---------------------------------------------------------------------------
// K6: hiddens transpose  outh[h, r] = g_hs[r, h]   (r = t*B+b)
// ---------------------------------------------------------------------------
__global__ void transpose_kernel(float* __restrict__ outh) {
    __shared__ float tile[32][33];
    const int h0 = blockIdx.x * 32;
    const int r0 = blockIdx.y * 32;
    const int tx = threadIdx.x;
    const int ty = threadIdx.y;
    #pragma unroll
    for (int i = 0; i < 32; i += 8)
        tile[ty + i][tx] = g_hs[(size_t)(r0 + ty + i) * Hd + h0 + tx];
    __syncthreads();
    #pragma unroll
    for (int i = 0; i < 32; i += 8)
        outh[(size_t)(h0 + ty + i) * BT + r0 + tx] = tile[tx][ty + i];
}

// ---------------------------------------------------------------------------
extern "C" void kernel_launch(void* const* d_in, const int* in_sizes, int n_in,
                              void* d_out, int out_size) {
    const int*   X   = nullptr;
    const float* wxh = nullptr;
    const float* whh = nullptr;
    const float* wvh = nullptr;
    const float* bv  = nullptr;
    const float* cv  = nullptr;

    for (int i = 0; i < n_in; i++) {
        int s = in_sizes[i];
        if (s == BT && !X)            X   = (const int*)d_in[i];
        else if (s == Hd * Hd)        whh = (const float*)d_in[i];
        else if (s == Hd)             bv  = (const float*)d_in[i];
        else if (s == Vd)             cv  = (const float*)d_in[i];
        else if (s == Vd * Hd) {
            if (!wxh) wxh = (const float*)d_in[i];
            else      wvh = (const float*)d_in[i];
        }
    }

    float* outp = (float*)d_out;
    float* outs = outp;                       // (B, T, V) log-probs
    float* outh = outp + (size_t)BT * Vd;     // (H, T, B) hiddens

    // persistent kernel needs 196,736 B dynamic smem (idempotent host call)
    cudaFuncSetAttribute(rnn_persistent,
                         cudaFuncAttributeMaxDynamicSharedMemorySize,
                         SM_TOT * (int)sizeof(float));

    // 1) embedding gather + bias
    embed_kernel<<<BT, 256>>>(X, wxh, bv);
    // 2) full recurrence in ONE persistent kernel (grid barrier between steps)
    rnn_persistent<<<NBLK, 512, SM_TOT * (int)sizeof(float)>>>(whh);
    // 3) output projection on tf32 tensor cores (writes z with row remap)
    vh_gemm_tf32<<<dim3(Vd / 128, BT / 128), 256>>>(wvh, cv, outs);
    // 4) log_softmax in place
    logsoftmax_kernel<<<BT, 256>>>(outs);
    // 5) hiddens transpose
    transpose_kernel<<<dim3(Hd / 32, BT / 32), dim3(32, 8)>>>(outh);
}

// round 8
// speedup vs baseline: 2.5787x; 1.2044x over previous
#include <cuda_runtime.h>
#include <math.h>
#include <stdint.h>

// Problem constants
#define Hd 1024
#define Vd 4096
#define Bd 64
#define Td 512
#define BT (Bd*Td)       // 32768
#define BdHd (Bd*Hd)
#define NBLK 128         // 4 groups x 32 CTAs
#define GSZ 32           // CTAs per group
#define GROWS 16         // batch rows per group
#define JPC 32           // j columns per CTA

// Scratch (device globals; no runtime allocation)
__device__ float g_abase[(size_t)BT*Hd];   // (t,b,h) pre-activation x_emb + b
__device__ float g_hs[(size_t)BT*Hd];      // (t,b,h) hidden states
__device__ unsigned g_gcnt[4*32];          // per-group barrier counters (128B apart)
__device__ unsigned g_ggen[4*32];          // per-group generations (128B apart)

// ---------------------------------------------------------------------------
// K1: embedding gather + bias  a_base[(t*B+b), :] = wxh[X[b,t], :] + bvec
// ---------------------------------------------------------------------------
__global__ void embed_kernel(const int* __restrict__ X,
                             const float* __restrict__ wxh,
                             const float* __restrict__ bvec) {
    int r = blockIdx.x;            // r = t*B + b
    int t = r >> 6;
    int b = r & 63;
    int row = X[b * Td + t];
    const float4* src = (const float4*)(wxh + (size_t)row * Hd);
    const float4* bb  = (const float4*)bvec;
    float4* dst = (float4*)(g_abase + (size_t)r * Hd);
    int i = threadIdx.x;           // 256 = H/4
    float4 v = src[i];
    float4 w = bb[i];
    v.x += w.x; v.y += w.y; v.z += w.z; v.w += w.w;
    dst[i] = v;
}

// ---------------------------------------------------------------------------
// Group barrier: 32 CTAs of one group. Sense-reversing (count,gen) on
// group-private 128B-separated lines. Deterministic, graph-replay safe.
// ---------------------------------------------------------------------------
__device__ __forceinline__ void group_barrier(int tid, int grp) {
    __syncthreads();
    if (tid == 0) {
        unsigned* cnt = &g_gcnt[grp * 32];
        unsigned* gnp = &g_ggen[grp * 32];
        unsigned gen = *(volatile unsigned*)gnp;      // read BEFORE arrive
        __threadfence();                              // publish CTA's writes
        unsigned p = atomicAdd(cnt, 1u);
        if (p == GSZ - 1u) {
            atomicExch(cnt, 0u);                      // reset for next use
            __threadfence();
            atomicExch(gnp, gen + 1u);                // release
        } else {
            while (*(volatile unsigned*)gnp == gen) { }
        }
        __threadfence();                              // acquire
    }
    __syncthreads();
}

// ---------------------------------------------------------------------------
// K2: persistent recurrence, batch-partitioned groups.
// Group g (32 CTAs) owns batch rows g*16..+16 for all 512 steps; within a
// group, CTA jc owns output cols jc*32..+32 and keeps its W_hh slice
// (32x1024 = 128KB) in smem. Per step: stage the group's h_{t-1} slice
// (16x1024 = 64KB) once; 16 warps = 8(j) x 2(b); 32 lanes split K 32 ways;
// thread computes 4j x 8b partial over its 32 Ks; butterfly-shuffle reduce
// over lanes; +a_base, tanh, scalar store; 32-CTA group barrier.
// Swizzle (f4 units): phys(u) = u ^ ((u>>3)&7), rows stride 256 f4.
// ---------------------------------------------------------------------------
__global__ void __launch_bounds__(512, 1)
rnn_persistent(const float* __restrict__ whh) {
    extern __shared__ float4 dsm4[];
    float4* Wsl = dsm4;             // [32 rows][256 f4] swizzled  (128 KB)
    float4* hsm = dsm4 + 8192;      // [16 rows][256 f4] swizzled  (64 KB)

    const int bid = blockIdx.x;     // 0..127
    const int grp = bid >> 5;       // 0..3
    const int jc  = bid & 31;       // 0..31
    const int j0  = jc * JPC;
    const int b0  = grp * GROWS;
    const int tid = threadIdx.x;
    const int w   = tid >> 5;       // warp 0..15
    const int ln  = tid & 31;
    const int jw  = w >> 1;         // 0..7  (4 cols each)
    const int bw  = w & 1;          // 0..1  (8 rows each)

    // Load W_hh slice rows j0..j0+31 (contiguous) into swizzled smem
    {
        const float4* wsrc = (const float4*)(whh + (size_t)j0 * Hd);
        #pragma unroll
        for (int q = 0; q < 16; q++) {
            int idx = tid + q * 512;             // 0..8191
            int r = idx >> 8, u = idx & 255;
            Wsl[r * 256 + (u ^ ((u >> 3) & 7))] = wsrc[idx];
        }
    }

    // h_0 = tanh(a_base[0]) for this CTA's owned (b,j): 16x32 = 1/thread
    {
        int r = tid >> 5, cc = tid & 31;
        size_t off = (size_t)(b0 + r) * Hd + j0 + cc;
        g_hs[off] = tanhf(g_abase[off]);
    }

    // per-thread output coordinates (after shuffle reduce, lane ln owns
    // idx=ln -> (m = ln>>3, i = ln&7))
    const int jo = j0 + jw * 4 + (ln >> 3);
    const int bo = b0 + bw * 8 + (ln & 7);

    for (int t = 1; t < Td; t++) {
        group_barrier(tid, grp);   // h_{t-1} of group visible; guards hsm reuse

        // prefetch a_base for this thread's output (hides DRAM latency)
        float abv = __ldg(&g_abase[(size_t)t * BdHd + (size_t)bo * Hd + jo]);

        // stage group's h_{t-1} slice: 4096 f4, 8 per thread, coalesced
        {
            const float4* hsrc = (const float4*)(g_hs + (size_t)(t - 1) * BdHd
                                                      + (size_t)b0 * Hd);
            float4 pf[8];
            #pragma unroll
            for (int q = 0; q < 8; q++) pf[q] = hsrc[tid + q * 512];
            #pragma unroll
            for (int q = 0; q < 8; q++) {
                int idx = tid + q * 512;
                int r = idx >> 8, u = idx & 255;
                hsm[r * 256 + (u ^ ((u >> 3) & 7))] = pf[q];
            }
        }
        __syncthreads();

        // compute: thread covers j = jw*4..+4, b = bw*8..+8, k = ln*32..+32
        float acc[32];
        #pragma unroll
        for (int e = 0; e < 32; e++) acc[e] = 0.0f;

        #pragma unroll
        for (int kc = 0; kc < 8; kc++) {
            const int up = ln * 8 + (kc ^ (ln & 7));   // swizzled f4 col
            float4 wv[4];
            #pragma unroll
            for (int m = 0; m < 4; m++)
                wv[m] = Wsl[(jw * 4 + m) * 256 + up];
            #pragma unroll
            for (int i = 0; i < 8; i++) {
                float4 hv = hsm[(bw * 8 + i) * 256 + up];
                #pragma unroll
                for (int m = 0; m < 4; m++) {
                    float s = acc[m * 8 + i];
                    s = fmaf(hv.x, wv[m].x, s);
                    s = fmaf(hv.y, wv[m].y, s);
                    s = fmaf(hv.z, wv[m].z, s);
                    s = fmaf(hv.w, wv[m].w, s);
                    acc[m * 8 + i] = s;
                }
            }
        }

        // butterfly shuffle reduction over 32 lanes (K partials).
        // Invariant: after round `off`, acc[i] (i<off) holds the sum over the
        // lane-pairs for output idx = (ln & ~(2*off-1) bits processed) + i.
        #pragma unroll
        for (int off = 16; off >= 1; off >>= 1) {
            #pragma unroll
            for (int i = 0; i < off; i++) {
                float send = (ln & off) ? acc[i] : acc[i + off];
                float keep = (ln & off) ? acc[i + off] : acc[i];
                acc[i] = keep + __shfl_xor_sync(0xffffffffu, send, off);
            }
        }
        // lane ln now holds the full K-sum for output (jo, bo)

        float hval = tanhf(acc[0] + abv);
        g_hs[(size_t)t * BdHd + (size_t)bo * Hd + jo] = hval;
        // group_barrier at next iteration guards hsm before overwrite
    }
}

// ---------------------------------------------------------------------------
// K4: output GEMM on tf32 tensor cores.
// z[r, v] = sum_k Hs[r,k] * Wvh[v,k] + c[v], row remap r=(t*B+b) -> (b*T+t).
// BM=128, BN=128, BK=16. 8 warps as 4(m) x 2(n); warp tile 32x64 =
// 2 x 8 tiles of m16n8k8. A row-major, B col-major (wvh rows ARE B columns).
// ---------------------------------------------------------------------------
__device__ __forceinline__ uint32_t f2tf32(float x) {
    uint32_t r;
    asm("cvt.rna.tf32.f32 %0, %1;" : "=r"(r) : "f"(x));
    return r;
}
__device__ __forceinline__ void mma_tf32(float c[4], uint32_t a0, uint32_t a1,
                                         uint32_t a2, uint32_t a3,
                                         uint32_t b0, uint32_t b1) {
    asm volatile(
        "mma.sync.aligned.m16n8k8.row.col.f32.tf32.tf32.f32 "
        "{%0,%1,%2,%3}, {%4,%5,%6,%7}, {%8,%9}, {%0,%1,%2,%3};"
        : "+f"(c[0]), "+f"(c[1]), "+f"(c[2]), "+f"(c[3])
        : "r"(a0), "r"(a1), "r"(a2), "r"(a3), "r"(b0), "r"(b1));
}

#define LDA 136   // pad: conflict-free fragment loads

__global__ void __launch_bounds__(256, 1)
vh_gemm_tf32(const float* __restrict__ wvh,
             const float* __restrict__ cvec,
             float* __restrict__ outp) {
    __shared__ uint32_t A_s[16][LDA];
    __shared__ uint32_t B_s[16][LDA];
    const int v0 = blockIdx.x * 128;
    const int r0 = blockIdx.y * 128;
    const int tid  = threadIdx.x;
    const int warp = tid >> 5;
    const int lane = tid & 31;
    const int warp_m = warp & 3;        // 4 m-warps
    const int warp_n = warp >> 2;       // 2 n-warps
    const int m_base = warp_m * 32;
    const int n_base = warp_n * 64;
    const int lq = lane >> 2;           // 0..7
    const int lr = lane & 3;            // 0..3

    float acc[2][8][4];
    #pragma unroll
    for (int mt = 0; mt < 2; mt++)
        #pragma unroll
        for (int nt = 0; nt < 8; nt++)
            #pragma unroll
            for (int e = 0; e < 4; e++) acc[mt][nt][e] = 0.0f;

    const int lrow = tid >> 2;          // 0..63
    const int lk4  = (tid & 3) * 4;

    for (int kc = 0; kc < 64; ++kc) {
        int k0 = kc * 16;
        float4 a0 = *(const float4*)(g_hs + (size_t)(r0 + lrow) * Hd + k0 + lk4);
        float4 a1 = *(const float4*)(g_hs + (size_t)(r0 + lrow + 64) * Hd + k0 + lk4);
        float4 b0 = *(const float4*)(wvh + (size_t)(v0 + lrow) * Hd + k0 + lk4);
        float4 b1 = *(const float4*)(wvh + (size_t)(v0 + lrow + 64) * Hd + k0 + lk4);
        __syncthreads();
        A_s[lk4 + 0][lrow] = f2tf32(a0.x); A_s[lk4 + 1][lrow] = f2tf32(a0.y);
        A_s[lk4 + 2][lrow] = f2tf32(a0.z); A_s[lk4 + 3][lrow] = f2tf32(a0.w);
        A_s[lk4 + 0][lrow + 64] = f2tf32(a1.x); A_s[lk4 + 1][lrow + 64] = f2tf32(a1.y);
        A_s[lk4 + 2][lrow + 64] = f2tf32(a1.z); A_s[lk4 + 3][lrow + 64] = f2tf32(a1.w);
        B_s[lk4 + 0][lrow] = f2tf32(b0.x); B_s[lk4 + 1][lrow] = f2tf32(b0.y);
        B_s[lk4 + 2][lrow] = f2tf32(b0.z); B_s[lk4 + 3][lrow] = f2tf32(b0.w);
        B_s[lk4 + 0][lrow + 64] = f2tf32(b1.x); B_s[lk4 + 1][lrow + 64] = f2tf32(b1.y);
        B_s[lk4 + 2][lrow + 64] = f2tf32(b1.z); B_s[lk4 + 3][lrow + 64] = f2tf32(b1.w);
        __syncthreads();

        #pragma unroll
        for (int ks = 0; ks < 2; ks++) {
            int kq = ks * 8 + lr;
            uint32_t afr[2][4];
            #pragma unroll
            for (int mt = 0; mt < 2; mt++) {
                int row = m_base + mt * 16 + lq;
                afr[mt][0] = A_s[kq][row];
                afr[mt][1] = A_s[kq][row + 8];
                afr[mt][2] = A_s[kq + 4][row];
                afr[mt][3] = A_s[kq + 4][row + 8];
            }
            uint32_t bfr[8][2];
            #pragma unroll
            for (int nt = 0; nt < 8; nt++) {
                int col = n_base + nt * 8 + lq;
                bfr[nt][0] = B_s[kq][col];
                bfr[nt][1] = B_s[kq + 4][col];
            }
            #pragma unroll
            for (int mt = 0; mt < 2; mt++)
                #pragma unroll
                for (int nt = 0; nt < 8; nt++)
                    mma_tf32(acc[mt][nt], afr[mt][0], afr[mt][1], afr[mt][2],
                             afr[mt][3], bfr[nt][0], bfr[nt][1]);
        }
    }

    // epilogue: add c, remap r=(t*B+b) -> (b*T+t), store float2 pairs
    #pragma unroll
    for (int nt = 0; nt < 8; nt++) {
        int col = n_base + nt * 8 + 2 * lr;
        float2 cv = *(const float2*)(cvec + v0 + col);
        #pragma unroll
        for (int mt = 0; mt < 2; mt++) {
            #pragma unroll
            for (int h = 0; h < 2; h++) {
                int r = r0 + m_base + mt * 16 + lq + h * 8;
                int orow = (r & 63) * Td + (r >> 6);   // b*T + t
                float2 o;
                o.x = acc[mt][nt][h * 2 + 0] + cv.x;
                o.y = acc[mt][nt][h * 2 + 1] + cv.y;
                *(float2*)(outp + (size_t)orow * Vd + v0 + col) = o;
            }
        }
    }
}

// ---------------------------------------------------------------------------
// K5: in-place log_softmax over rows of 4096. One block (256 thr) per row.
// ---------------------------------------------------------------------------
__global__ void logsoftmax_kernel(float* __restrict__ outp) {
    float* row = outp + (size_t)blockIdx.x * Vd;
    const int tid = threadIdx.x;
    const int lane = tid & 31;
    const int wid = tid >> 5;
    __shared__ float sred[8];

    float4 v[4];
    float mx = -1e30f;
    #pragma unroll
    for (int i = 0; i < 4; i++) {
        v[i] = *(const float4*)(row + (i * 256 + tid) * 4);
        mx = fmaxf(mx, fmaxf(fmaxf(v[i].x, v[i].y), fmaxf(v[i].z, v[i].w)));
    }
    #pragma unroll
    for (int o = 16; o; o >>= 1) mx = fmaxf(mx, __shfl_xor_sync(0xffffffffu, mx, o));
    if (lane == 0) sred[wid] = mx;
    __syncthreads();
    float m2 = sred[lane & 7];
    #pragma unroll
    for (int o = 4; o; o >>= 1) m2 = fmaxf(m2, __shfl_xor_sync(0xffffffffu, m2, o));
    mx = m2;
    __syncthreads();

    float sum = 0.0f;
    #pragma unroll
    for (int i = 0; i < 4; i++) {
        sum += expf(v[i].x - mx) + expf(v[i].y - mx)
             + expf(v[i].z - mx) + expf(v[i].w - mx);
    }
    #pragma unroll
    for (int o = 16; o; o >>= 1) sum += __shfl_xor_sync(0xffffffffu, sum, o);
    if (lane == 0) sred[wid] = sum;
    __syncthreads();
    float s2 = sred[lane & 7];
    #pragma unroll
    for (int o = 4; o; o >>= 1) s2 += __shfl_xor_sync(0xffffffffu, s2, o);

    float lse = mx + logf(s2);
    #pragma unroll
    for (int i = 0; i < 4; i++) {
        v[i].x -= lse; v[i].y -= lse; v[i].z -= lse; v[i].w -= lse;
        *(float4*)(row + (i * 256 + tid) * 4) = v[i];
    }
}

// ---------------------------------------------------------------------------
// K6: hiddens transpose  outh[h, r] = g_hs[r, h]   (r = t*B+b)
// ---------------------------------------------------------------------------
__global__ void transpose_kernel(float* __restrict__ outh) {
    __shared__ float tile[32][33];
    const int h0 = blockIdx.x * 32;
    const int r0 = blockIdx.y * 32;
    const int tx = threadIdx.x;
    const int ty = threadIdx.y;
    #pragma unroll
    for (int i = 0; i < 32; i += 8)
        tile[ty + i][tx] = g_hs[(size_t)(r0 + ty + i) * Hd + h0 + tx];
    __syncthreads();
    #pragma unroll
    for (int i = 0; i < 32; i += 8)
        outh[(size_t)(h0 + ty + i) * BT + r0 + tx] = tile[tx][ty + i];
}

// ---------------------------------------------------------------------------
extern "C" void kernel_launch(void* const* d_in, const int* in_sizes, int n_in,
                              void* d_out, int out_size) {
    const int*   X   = nullptr;
    const float* wxh = nullptr;
    const float* whh = nullptr;
    const float* wvh = nullptr;
    const float* bv  = nullptr;
    const float* cv  = nullptr;

    for (int i = 0; i < n_in; i++) {
        int s = in_sizes[i];
        if (s == BT && !X)            X   = (const int*)d_in[i];
        else if (s == Hd * Hd)        whh = (const float*)d_in[i];
        else if (s == Hd)             bv  = (const float*)d_in[i];
        else if (s == Vd)             cv  = (const float*)d_in[i];
        else if (s == Vd * Hd) {
            if (!wxh) wxh = (const float*)d_in[i];
            else      wvh = (const float*)d_in[i];
        }
    }

    float* outp = (float*)d_out;
    float* outs = outp;                       // (B, T, V) log-probs
    float* outh = outp + (size_t)BT * Vd;     // (H, T, B) hiddens

    // persistent kernel needs 192 KB dynamic smem (idempotent host call)
    const int rnn_smem = (8192 + 4096) * 16;  // 196,608 B
    cudaFuncSetAttribute(rnn_persistent,
                         cudaFuncAttributeMaxDynamicSharedMemorySize, rnn_smem);

    // 1) embedding gather + bias
    embed_kernel<<<BT, 256>>>(X, wxh, bv);
    // 2) recurrence: 4 independent batch groups, 32-CTA group barriers only
    rnn_persistent<<<NBLK, 512, rnn_smem>>>(whh);
    // 3) output projection on tf32 tensor cores (writes z with row remap)
    vh_gemm_tf32<<<dim3(Vd / 128, BT / 128), 256>>>(wvh, cv, outs);
    // 4) log_softmax in place
    logsoftmax_kernel<<<BT, 256>>>(outs);
    // 5) hiddens transpose
    transpose_kernel<<<dim3(Hd / 32, BT / 32), dim3(32, 8)>>>(outh);
}